// round 7
// baseline (speedup 1.0000x reference)
#include <cuda_runtime.h>
#include <cuda_bf16.h>
#include <math.h>

#define N_USER 100000
#define N_ITEM 60000
#define NN     160000      // total nodes
#define NNZ_E  2000000
#define BB     16384
#define DD     64

typedef unsigned long long u64;

// ---------------- device scratch (static, allocation-free) ----------------
__device__ float g_ego [(size_t)NN * DD];        // 41 MB
__device__ float g_side[(size_t)NN * DD];        // 41 MB
__device__ float g_alle[(size_t)NN * 4 * DD];    // 164 MB  [node][256]
__device__ int   g_cnt   [NN];                   // zeroed by k_scan each exec
__device__ int   g_off   [NN + 1];
__device__ int   g_cursor[NN];
__device__ int2  g_cv    [NNZ_E];                // packed (col, val-bits)

// ---------------- f32x2 packed helpers -------------------------------------
__device__ __forceinline__ u64 pack2(float x, float y) {
    u64 r;
    asm("mov.b64 %0, {%1, %2};" : "=l"(r) : "f"(x), "f"(y));
    return r;
}
__device__ __forceinline__ float2 unpack2(u64 v) {
    float2 r;
    asm("mov.b64 {%0, %1}, %2;" : "=f"(r.x), "=f"(r.y) : "l"(v));
    return r;
}
__device__ __forceinline__ void ffma2(u64& d, u64 a, u64 b) {
    asm("fma.rn.f32x2 %0, %1, %2, %0;" : "+l"(d) : "l"(a), "l"(b));
}

// ------- fused init + hist: g_cnt is zero on entry (BSS / k_scan post-zero)
__global__ void k_inithist(const float* __restrict__ ue, const float* __restrict__ ie,
                           const int* __restrict__ rows) {
    int idx = blockIdx.x * blockDim.x + threadIdx.x;
    if (idx < NN * DD / 4) {
        int fidx = idx << 2;
        int node = fidx >> 6;
        int d    = fidx & 63;
        float4 v = (node < N_USER) ? ((const float4*)ue)[idx]
                                   : *(const float4*)&ie[fidx - N_USER * DD];
        *(float4*)&g_ego[fidx] = v;
        *(float4*)&g_alle[(size_t)node * 256 + d] = v;
    }
    if (idx < NNZ_E) atomicAdd(&g_cnt[rows[idx]], 1);
}

// single-block exclusive scan over g_cnt -> g_off, g_cursor; re-zeroes g_cnt
__global__ void k_scan() {
    const int CH = (NN + 1023) >> 10;   // 157
    int t = threadIdx.x;
    int b0 = t * CH;
    int b1 = b0 + CH; if (b1 > NN) b1 = NN;
    if (b0 > NN) b0 = NN;

    int s = 0;
    for (int i = b0; i < b1; i++) s += g_cnt[i];

    __shared__ int wsum[32];
    int lane = t & 31, wid = t >> 5;
    int v = s;
    #pragma unroll
    for (int o = 1; o < 32; o <<= 1) {
        int u = __shfl_up_sync(0xffffffffu, v, o);
        if (lane >= o) v += u;
    }
    if (lane == 31) wsum[wid] = v;
    __syncthreads();
    if (wid == 0) {
        int w = wsum[lane];
        #pragma unroll
        for (int o = 1; o < 32; o <<= 1) {
            int u = __shfl_up_sync(0xffffffffu, w, o);
            if (lane >= o) w += u;
        }
        wsum[lane] = w;  // inclusive warp sums
    }
    __syncthreads();
    int excl = v - s + (wid > 0 ? wsum[wid - 1] : 0);
    int off = excl;
    for (int i = b0; i < b1; i++) {
        g_off[i] = off;
        g_cursor[i] = off;
        int c = g_cnt[i];
        g_cnt[i] = 0;            // ready for next graph replay
        off += c;
    }
    if (t == 1023) g_off[NN] = off;   // == NNZ_E
}

__global__ void k_fill(const int* __restrict__ rows, const int* __restrict__ cols,
                       const float* __restrict__ vals) {
    int e = blockIdx.x * blockDim.x + threadIdx.x;
    if (e < NNZ_E) {
        int r = rows[e];
        int p = atomicAdd(&g_cursor[r], 1);
        g_cv[p] = make_int2(cols[e], __float_as_int(vals[e]));
    }
}

// ---------------- SpMM v3: warp per row, lane owns u64 (2 cols) ------------
// side[r] = sum_e val*ego[col].  One edge = broadcast header + LDG.64 gather
// + FFMA2. No reduction shuffles. Unroll 4 edges for MLP.
__global__ void k_spmm() {
    int w = (blockIdx.x * blockDim.x + threadIdx.x) >> 5;
    if (w >= NN) return;
    int lane = threadIdx.x & 31;
    int s = g_off[w], e = g_off[w + 1];
    const u64* __restrict__ ego = (const u64*)g_ego;
    u64 acc = 0;
    int idx = s;
    for (; idx + 4 <= e; idx += 4) {
        int2 c0 = g_cv[idx];
        int2 c1 = g_cv[idx + 1];
        int2 c2 = g_cv[idx + 2];
        int2 c3 = g_cv[idx + 3];
        u64 g0 = ego[(size_t)c0.x * 32 + lane];
        u64 g1 = ego[(size_t)c1.x * 32 + lane];
        u64 g2 = ego[(size_t)c2.x * 32 + lane];
        u64 g3 = ego[(size_t)c3.x * 32 + lane];
        float v0 = __int_as_float(c0.y);
        float v1 = __int_as_float(c1.y);
        float v2 = __int_as_float(c2.y);
        float v3 = __int_as_float(c3.y);
        ffma2(acc, pack2(v0, v0), g0);
        ffma2(acc, pack2(v1, v1), g1);
        ffma2(acc, pack2(v2, v2), g2);
        ffma2(acc, pack2(v3, v3), g3);
    }
    for (; idx < e; idx++) {
        int2 cv = g_cv[idx];
        u64 g = ego[(size_t)cv.x * 32 + lane];
        float v = __int_as_float(cv.y);
        ffma2(acc, pack2(v, v), g);
    }
    ((u64*)g_side)[(size_t)w * 32 + lane] = acc;   // coalesced 256B/warp
}

// ---------------- transform v3: occupancy-first ----------------------------
// block = 256 thr = 8 warps covers 64 rows. warp w: colgroup=(w&3)*16,
// rowhalf rh=(w>>2) in {0,1}: row = rh*32+lane. Each (rh,cg) warp does
// 32 rows x 16 cols. acc = 16 floats = 8 u64. W cached in shared.
// smem ~67KB -> 3 blocks/SM (24 warps/SM).
#define TR_SMEM_FLOATS (64*65 + 64*65 + 4096 + 4096 + 4*64 + 64)
__global__ __launch_bounds__(256) void k_transform(
        const float* __restrict__ Wg, const float* __restrict__ bg,
        const float* __restrict__ Wb, const float* __restrict__ bb,
        int layer) {
    extern __shared__ float smem[];
    float (*sS)[65] = (float(*)[65])smem;
    float (*sE)[65] = (float(*)[65])(smem + 64 * 65);
    float* sWg = smem + 2 * 64 * 65;
    float* sWb = sWg + 4096;
    float* sP  = sWb + 4096;        // [4][64]
    float* sInv = sP + 4 * 64;      // [64]

    int r0 = blockIdx.x * 64;
    int t = threadIdx.x;
    int w = t >> 5, lane = t & 31;

    // stage side/ego tiles (64 rows x 64 cols)
    for (int i = t; i < 1024; i += 256) {
        int rr = i >> 4, c4 = (i & 15) << 2;
        float4 a = *(const float4*)&g_side[(size_t)(r0 + rr) * DD + c4];
        float4 b = *(const float4*)&g_ego [(size_t)(r0 + rr) * DD + c4];
        sS[rr][c4] = a.x; sS[rr][c4+1] = a.y; sS[rr][c4+2] = a.z; sS[rr][c4+3] = a.w;
        sE[rr][c4] = b.x; sE[rr][c4+1] = b.y; sE[rr][c4+2] = b.z; sE[rr][c4+3] = b.w;
    }
    // stage W (two 64x64 matrices for this layer)
    for (int i = t; i < 1024; i += 256) {
        ((float4*)sWg)[i] = ((const float4*)(Wg + layer * 4096))[i];
        ((float4*)sWb)[i] = ((const float4*)(Wb + layer * 4096))[i];
    }
    __syncthreads();

    int cg = w & 3;
    int rh = w >> 2;
    int row = rh * 32 + lane;
    int j0 = cg * 16;

    u64 acc[8];
    #pragma unroll
    for (int v = 0; v < 8; v++) {
        float bx = bg[layer * 64 + j0 + 2*v]     + bb[layer * 64 + j0 + 2*v];
        float by = bg[layer * 64 + j0 + 2*v + 1] + bb[layer * 64 + j0 + 2*v + 1];
        acc[v] = pack2(bx, by);
    }

    #pragma unroll 4
    for (int i = 0; i < 64; i++) {
        float si = sS[row][i];
        float bi = sE[row][i] * si;
        u64 sp = pack2(si, si), bp = pack2(bi, bi);
        const u64* pg = (const u64*)&sWg[i * 64 + j0];   // uniform broadcast
        const u64* pb = (const u64*)&sWb[i * 64 + j0];
        #pragma unroll
        for (int v = 0; v < 8; v++) {
            ffma2(acc[v], sp, pg[v]);
            ffma2(acc[v], bp, pb[v]);
        }
    }

    // leaky relu + per-row sumsq partial
    float ss = 0.f;
    #pragma unroll
    for (int v = 0; v < 8; v++) {
        float2 x = unpack2(acc[v]);
        x.x = (x.x > 0.f) ? x.x : 0.2f * x.x;
        x.y = (x.y > 0.f) ? x.y : 0.2f * x.y;
        acc[v] = pack2(x.x, x.y);
        ss = fmaf(x.x, x.x, fmaf(x.y, x.y, ss));
    }
    sP[cg * 64 + row] = ss;
    __syncthreads();            // all reads of sS/sE and writes of sP done

    if (t < 64) {
        float tot = sP[t] + sP[64 + t] + sP[128 + t] + sP[192 + t];
        sInv[t] = 1.0f / fmaxf(sqrtf(tot), 1e-12f);
    }
    // stash activations into sE for coalesced writeback
    #pragma unroll
    for (int v = 0; v < 8; v++) {
        float2 x = unpack2(acc[v]);
        sE[row][j0 + 2*v]     = x.x;
        sE[row][j0 + 2*v + 1] = x.y;
    }
    __syncthreads();

    for (int i = t; i < 1024; i += 256) {
        int rr = i >> 4, c4 = (i & 15) << 2;
        float inv = sInv[rr];
        float4 o;
        o.x = sE[rr][c4]; o.y = sE[rr][c4+1]; o.z = sE[rr][c4+2]; o.w = sE[rr][c4+3];
        *(float4*)&g_ego[(size_t)(r0 + rr) * DD + c4] = o;
        float4 n; n.x = o.x*inv; n.y = o.y*inv; n.z = o.z*inv; n.w = o.w*inv;
        *(float4*)&g_alle[(size_t)(r0 + rr) * 256 + (size_t)(layer + 1) * 64 + c4] = n;
    }
}

// ---------------- predict: warp per batch element -------------------------
__global__ void k_pred(const int* __restrict__ users, const int* __restrict__ items,
                       const float* __restrict__ pW, const float* __restrict__ pb,
                       float* __restrict__ out) {
    int w = (blockIdx.x * blockDim.x + threadIdx.x) >> 5;
    if (w >= BB) return;
    int lane = threadIdx.x & 31;
    size_t u = (size_t)users[w];
    size_t v = (size_t)N_USER + (size_t)items[w];
    const float* pu = &g_alle[u * 256 + lane * 8];
    const float* pv = &g_alle[v * 256 + lane * 8];
    const float* pw = pW + lane * 8;
    float acc = 0.f;
    #pragma unroll
    for (int q = 0; q < 8; q++) acc = fmaf(pu[q] * pv[q], pw[q], acc);
    #pragma unroll
    for (int o = 16; o > 0; o >>= 1) acc += __shfl_xor_sync(0xffffffffu, acc, o);
    if (lane == 0) out[w] = 1.0f / (1.0f + expf(-(acc + pb[0])));
}

// ---------------- launch ---------------------------------------------------
extern "C" void kernel_launch(void* const* d_in, const int* in_sizes, int n_in,
                              void* d_out, int out_size) {
    const int*   users = (const int*)  d_in[0];
    const int*   items = (const int*)  d_in[1];
    const int*   arows = (const int*)  d_in[2];
    const int*   acols = (const int*)  d_in[3];
    const float* avals = (const float*)d_in[4];
    const float* ue    = (const float*)d_in[5];
    const float* ie    = (const float*)d_in[6];
    const float* Wg    = (const float*)d_in[7];
    const float* bg    = (const float*)d_in[8];
    const float* Wb    = (const float*)d_in[9];
    const float* bb    = (const float*)d_in[10];
    const float* pW    = (const float*)d_in[11];
    const float* pb    = (const float*)d_in[12];
    float* out = (float*)d_out;

    const int tr_smem = TR_SMEM_FLOATS * 4;   // ~67.3 KB -> 3 blocks/SM
    cudaFuncSetAttribute(k_transform, cudaFuncAttributeMaxDynamicSharedMemorySize, tr_smem);

    k_inithist<<<(NN * DD / 4 + 255) / 256, 256>>>(ue, ie, arows);
    k_scan<<<1, 1024>>>();
    k_fill<<<(NNZ_E + 255) / 256, 256>>>(arows, acols, avals);

    for (int k = 0; k < 3; k++) {
        k_spmm<<<NN / 8, 256>>>();                        // warp per row
        k_transform<<<NN / 64, 256, tr_smem>>>(Wg, bg, Wb, bb, k);
    }

    k_pred<<<(BB * 32) / 256, 256>>>(users, items, pW, pb, out);
}